// round 8
// baseline (speedup 1.0000x reference)
#include <cuda_runtime.h>

// ConstituencyMFVI: B=8, N=192, 3 iterations.
// Persistent kernel, 768 threads. Tile register-resident; loads are
// COALESCED LDG.128 direct to registers (no cp.async -> no LDGSTS issue
// bottleneck, which was the R7 limiter at ~9K cyc/tile).
// Warp w owns rows j = 8w + 4h + t (h = half-warp, t = 0..3); lane ll in
// [0,16) holds f4 columns {ll, ll+16, ll+32} of each row. Per-row dot =
// 12 FMA + 4-step shfl_xor reduce (both halves reduce concurrently).
// Mask terms k==i, k==j: combiner thread jj prefetches row[i], row[jj]
// once per tile and subtracts sig[i]*vi + sig_prev*vjj each iteration.
// SMEM: sig[2][192] + partial[192] only (~2.3 KB).

#define NDIM    192
#define THREADS 768
#define NTILES  (8 * NDIM)   // 1536

__device__ __forceinline__ float sigmoidf_(float x) {
    return 1.0f / (1.0f + __expf(-x));
}

__global__ void __launch_bounds__(THREADS, 1)
mfvi_kernel(const float* __restrict__ s_span,
            const float* __restrict__ s_pair,
            float* __restrict__ out)
{
    __shared__ float sigA[NDIM];
    __shared__ float sigB[NDIM];
    __shared__ float partial[NDIM];

    const int tid = threadIdx.x;
    const int w   = tid >> 5;          // warp 0..23
    const int l   = tid & 31;
    const int h   = l >> 4;            // half-warp
    const int ll  = l & 15;            // lane within half

    for (int g = blockIdx.x; g < NTILES; g += gridDim.x) {
        const int i = g % NDIM;
        const float* gbase = s_pair + (size_t)g * (NDIM * NDIM);

        // ---- Load rows j = 8w+4h+t into registers (coalesced LDG.128) ----
        float4 v[4][3];
        #pragma unroll
        for (int t = 0; t < 4; ++t) {
            const int j = 8 * w + 4 * h + t;
            const float4* rowp =
                reinterpret_cast<const float4*>(gbase + (size_t)j * NDIM);
            if (j > i) {
                v[t][0] = __ldg(rowp + ll);
                v[t][1] = __ldg(rowp + ll + 16);
                v[t][2] = __ldg(rowp + ll + 32);
            } else {
                v[t][0] = v[t][1] = v[t][2] = make_float4(0.f, 0.f, 0.f, 0.f);
            }
        }

        // ---- Combiner state: span, sig0, mask-correction scalars ----
        float span_j = 0.0f, s_prev = 0.5f, vi = 0.0f, vjj = 0.0f;
        if (tid < NDIM) {
            span_j = s_span[(size_t)g * NDIM + tid];
            s_prev = sigmoidf_(span_j);
            sigA[tid] = s_prev;
            if (tid > i) {
                vi  = __ldg(gbase + (size_t)tid * NDIM + i);
                vjj = __ldg(gbase + (size_t)tid * NDIM + tid);
            }
        }
        __syncthreads();

        // ---- 3 mean-field iterations ----
        #pragma unroll
        for (int it = 0; it < 3; ++it) {
            const float* sg = (it & 1) ? sigB : sigA;
            const float4* sg4 = reinterpret_cast<const float4*>(sg);
            const float4 s0 = sg4[ll];
            const float4 s1 = sg4[ll + 16];
            const float4 s2 = sg4[ll + 32];

            float d[4];
            #pragma unroll
            for (int t = 0; t < 4; ++t) {
                d[t] = v[t][0].x * s0.x + v[t][0].y * s0.y
                     + v[t][0].z * s0.z + v[t][0].w * s0.w
                     + v[t][1].x * s1.x + v[t][1].y * s1.y
                     + v[t][1].z * s1.z + v[t][1].w * s1.w
                     + v[t][2].x * s2.x + v[t][2].y * s2.y
                     + v[t][2].z * s2.z + v[t][2].w * s2.w;
            }
            #pragma unroll
            for (int off = 8; off >= 1; off >>= 1) {
                #pragma unroll
                for (int t = 0; t < 4; ++t)
                    d[t] += __shfl_xor_sync(0xffffffffu, d[t], off);
            }
            #pragma unroll
            for (int t = 0; t < 4; ++t)
                if (ll == t) partial[8 * w + 4 * h + t] = d[t];
            __syncthreads();

            if (tid < NDIM) {
                float o;
                if (tid > i) {
                    const float q = span_j + partial[tid]
                                  - sg[i] * vi - s_prev * vjj;
                    o = sigmoidf_(q);
                } else {
                    o = s_prev;      // rows j<=i: q stays = span
                }
                s_prev = o;
                if (it == 2) out[(size_t)g * NDIM + tid] = o;
                else         ((it & 1) ? sigA : sigB)[tid] = o;
            }
            __syncthreads();
        }
    }
}

extern "C" void kernel_launch(void* const* d_in, const int* in_sizes, int n_in,
                              void* d_out, int out_size)
{
    (void)in_sizes; (void)n_in; (void)out_size;
    const float* s_span = (const float*)d_in[0];
    const float* s_pair = (const float*)d_in[1];
    // d_in[2] = mask: analytic (strict upper triangle), not needed.
    float* out = (float*)d_out;

    int nsm = 148;
    cudaDeviceGetAttribute(&nsm, cudaDevAttrMultiProcessorCount, 0);
    if (nsm <= 0 || nsm > NTILES) nsm = 148;

    mfvi_kernel<<<nsm, THREADS>>>(s_span, s_pair, out);
}

// round 9
// speedup vs baseline: 1.1496x; 1.1496x over previous
#include <cuda_runtime.h>

// ConstituencyMFVI: B=8, N=192, 3 iterations.
// Persistent CTA (grid = #SMs), 512 threads => 128-reg/thread cap, so the
// 72-float/thread tile slice genuinely stays in registers (R7/R8 at 768
// threads hit the 80-reg cap and spilled).
// Pipeline per tile: coalesced cp.async gmem->SMEM (4 chunks of 48 rows,
// pad 196); iteration 1 fused into the SMEM->register consume; iterations
// 2-3 from registers; next tile's cp.async issued before iters 2-3.
// Layout: half-warp hw (0..31) owns local rows {6hw..6hw+5}; lane ll (0..15)
// holds f4 cols {ll, ll+16, ll+32}. Row dot = 12 FMA + 4-step shfl_xor.
// Mask terms: q -= sig0[i]*row[i] + sig_prev[j]*row[j] (sig[i] constant).

#define NDIM    192
#define RPAD    196
#define CHROWS  48
#define THREADS 512
#define NTILES  (8 * NDIM)   // 1536

static const int CHUNK_FLOATS = CHROWS * RPAD;   // 9408
static const int SMEM_BYTES   = (4 * CHUNK_FLOATS + 3 * NDIM) * 4;  // ~152.1KB

__device__ __forceinline__ unsigned smem_u32(const void* p) {
    return (unsigned)__cvta_generic_to_shared(p);
}
__device__ __forceinline__ float sigmoidf_(float x) {
    return 1.0f / (1.0f + __expf(-x));
}

// Issue 4 cp.async commit groups for tile g (empty commits keep the
// wait_group accounting consistent when g is out of range).
__device__ __forceinline__ void issue_tile(const float* __restrict__ s_pair,
                                           int g, int row0, int col, int tid,
                                           float* buf)
{
    const bool valid = (g < NTILES);
    const int  i = valid ? (g % NDIM) : (NDIM - 1);
    const int  rowStart = i + 1;
    const int  nRows    = NDIM - rowStart;
    const float* gbase  = s_pair + (size_t)g * (NDIM * NDIM);

    #pragma unroll
    for (int c = 0; c < 4; ++c) {
        int cr = nRows - c * CHROWS;            // rows in this chunk
        if (cr > CHROWS) cr = CHROWS;
        if (valid && cr > 0 && tid < 480) {
            const float* gsrc = gbase + (size_t)(rowStart + c * CHROWS) * NDIM;
            float* sdst = buf + c * CHUNK_FLOATS;
            #pragma unroll
            for (int p = 0; p < 5; ++p) {       // rows row0, row0+10, ...
                int r = row0 + 10 * p;
                if (r < cr) {
                    const float* src = gsrc + (size_t)r * NDIM + 4 * col;
                    unsigned dst = smem_u32(sdst + r * RPAD + 4 * col);
                    asm volatile("cp.async.cg.shared.global [%0], [%1], 16;"
                                 :: "r"(dst), "l"(src));
                }
            }
        }
        asm volatile("cp.async.commit_group;");
    }
}

__global__ void __launch_bounds__(THREADS, 1)
mfvi_kernel(const float* __restrict__ s_span,
            const float* __restrict__ s_pair,
            float* __restrict__ out)
{
    extern __shared__ float smem[];
    float* buf     = smem;                      // 4 chunks [48][196]
    float* sigA    = smem + 4 * CHUNK_FLOATS;   // [192]
    float* sigB    = sigA + NDIM;               // [192]
    float* partial = sigB + NDIM;               // [192] (local-row indexed)

    const int tid = threadIdx.x;
    const int hw  = tid >> 4;          // half-warp 0..31: owns rows 6hw..6hw+5
    const int ll  = tid & 15;
    const int myChunk = hw >> 3;       // chunk containing this thread's rows
    const int row0 = tid / 48;         // copy mapping (tid < 480)
    const int col  = tid % 48;

    issue_tile(s_pair, blockIdx.x, row0, col, tid, buf);

    for (int g = blockIdx.x; g < NTILES; g += gridDim.x) {
        const int i        = g % NDIM;
        const int rowStart = i + 1;
        const float* gbase = s_pair + (size_t)g * (NDIM * NDIM);

        // span / sig0 / mask-correction scalars (combiner threads)
        float span_j = 0.0f, s_prev = 0.5f, vi = 0.0f, vjj = 0.0f;
        if (tid < NDIM) {
            span_j = s_span[(size_t)g * NDIM + tid];
            s_prev = sigmoidf_(span_j);
            sigA[tid] = s_prev;
            sigB[tid] = s_prev;
            if (tid > i) {
                vi  = __ldg(gbase + (size_t)tid * NDIM + i);
                vjj = __ldg(gbase + (size_t)tid * NDIM + tid);
            }
        }

        // ---- Iteration 1 fused with SMEM->register consume ----
        float4 v[6][3];
        float  d[6];
        #pragma unroll
        for (int c = 0; c < 4; ++c) {
            if      (c == 0) asm volatile("cp.async.wait_group 3;");
            else if (c == 1) asm volatile("cp.async.wait_group 2;");
            else if (c == 2) asm volatile("cp.async.wait_group 1;");
            else             asm volatile("cp.async.wait_group 0;");
            __syncthreads();
            if (myChunk == c) {
                const float4* sg4 = reinterpret_cast<const float4*>(sigA);
                const float4 s0 = sg4[ll], s1 = sg4[ll + 16], s2 = sg4[ll + 32];
                #pragma unroll
                for (int t = 0; t < 6; ++t) {
                    const float* row = buf + c * CHUNK_FLOATS
                                     + (6 * (hw - 8 * c) + t) * RPAD;
                    float4 a = *reinterpret_cast<const float4*>(row + 4 * ll);
                    float4 b = *reinterpret_cast<const float4*>(row + 4 * (ll + 16));
                    float4 e = *reinterpret_cast<const float4*>(row + 4 * (ll + 32));
                    v[t][0] = a; v[t][1] = b; v[t][2] = e;
                    d[t] = a.x * s0.x + a.y * s0.y + a.z * s0.z + a.w * s0.w
                         + b.x * s1.x + b.y * s1.y + b.z * s1.z + b.w * s1.w
                         + e.x * s2.x + e.y * s2.y + e.z * s2.z + e.w * s2.w;
                }
                #pragma unroll
                for (int off = 8; off >= 1; off >>= 1)
                    #pragma unroll
                    for (int t = 0; t < 6; ++t)
                        d[t] += __shfl_xor_sync(0xffffffffu, d[t], off);
                #pragma unroll
                for (int t = 0; t < 6; ++t)
                    if (ll == t) partial[6 * hw + t] = d[t];
            }
        }
        __syncthreads();

        const float s0i = sigA[i];     // sig[i] never updates (i <= i)
        if (tid < NDIM && tid > i) {
            float q = span_j + partial[tid - rowStart] - s0i * vi - s_prev * vjj;
            s_prev = sigmoidf_(q);
            sigB[tid] = s_prev;
        }
        __syncthreads();

        // Buffers consumed -> overlap next tile's DRAM fetch with iters 2-3.
        issue_tile(s_pair, g + gridDim.x, row0, col, tid, buf);

        // ---- Iterations 2 and 3, from registers ----
        #pragma unroll
        for (int it = 0; it < 2; ++it) {
            const float4* sg4 =
                reinterpret_cast<const float4*>(it == 0 ? sigB : sigA);
            const float4 s0 = sg4[ll], s1 = sg4[ll + 16], s2 = sg4[ll + 32];
            #pragma unroll
            for (int t = 0; t < 6; ++t) {
                d[t] = v[t][0].x * s0.x + v[t][0].y * s0.y
                     + v[t][0].z * s0.z + v[t][0].w * s0.w
                     + v[t][1].x * s1.x + v[t][1].y * s1.y
                     + v[t][1].z * s1.z + v[t][1].w * s1.w
                     + v[t][2].x * s2.x + v[t][2].y * s2.y
                     + v[t][2].z * s2.z + v[t][2].w * s2.w;
            }
            #pragma unroll
            for (int off = 8; off >= 1; off >>= 1)
                #pragma unroll
                for (int t = 0; t < 6; ++t)
                    d[t] += __shfl_xor_sync(0xffffffffu, d[t], off);
            #pragma unroll
            for (int t = 0; t < 6; ++t)
                if (ll == t) partial[6 * hw + t] = d[t];
            __syncthreads();

            if (tid < NDIM && tid > i) {
                float q = span_j + partial[tid - rowStart]
                        - s0i * vi - s_prev * vjj;
                s_prev = sigmoidf_(q);
                if (it == 0) sigA[tid] = s_prev;
            }
            if (it == 1 && tid < NDIM)
                out[(size_t)g * NDIM + tid] = s_prev;  // j<=i rows keep s0
            __syncthreads();
        }
    }
}

extern "C" void kernel_launch(void* const* d_in, const int* in_sizes, int n_in,
                              void* d_out, int out_size)
{
    (void)in_sizes; (void)n_in; (void)out_size;
    const float* s_span = (const float*)d_in[0];
    const float* s_pair = (const float*)d_in[1];
    // d_in[2] = mask: analytic (strict upper triangle), not needed.
    float* out = (float*)d_out;

    int nsm = 148;
    cudaDeviceGetAttribute(&nsm, cudaDevAttrMultiProcessorCount, 0);
    if (nsm <= 0 || nsm > NTILES) nsm = 148;

    cudaFuncSetAttribute(mfvi_kernel,
                         cudaFuncAttributeMaxDynamicSharedMemorySize, SMEM_BYTES);

    mfvi_kernel<<<nsm, THREADS, SMEM_BYTES>>>(s_span, s_pair, out);
}

// round 10
// speedup vs baseline: 1.6546x; 1.4393x over previous
#include <cuda_runtime.h>
#include <cstdint>

// ConstituencyMFVI: B=8, N=192, 3 iterations.
// Persistent CTA per SM, 768 threads.
// KEY FIX: tile loads use cp.async.bulk (TMA) -- 3 instructions per tile
// instead of ~4600 LDGSTS (whose 8cyc/op issue cost was the hidden limiter
// of every previous round at ~9K cyc/tile).
// Tile rows i+1..191 live UNPADDED [r][192] in SMEM; consume is half-warp-
// per-row (lane ll reads f4 cols {ll,ll+16,ll+32}; contiguous -> conflict-
// free) + 4-step shfl_xor reduce. Rows >144 (only when i<47) are dotted
// from gmem/L2 each iteration.
// Ping-pong tile buffers: next tile's bulk copy issued at start of current
// tile's compute -> DRAM fully overlapped. mbarrier phase = (n/2)&1.

#define NDIM    192
#define CROWS   144          // rows cached in SMEM per tile
#define CHROWS  48           // rows per bulk-copy chunk (3 chunks)
#define THREADS 768
#define NTILES  (8 * NDIM)   // 1536

#define BUF_FLOATS (CROWS * NDIM)        // 27648
// smem: [16 floats mbar area][2 x BUF][sigA][sigB][partial]
static const int MBARF      = 16;
static const int SMEM_BYTES = (MBARF + 2 * BUF_FLOATS + 3 * NDIM) * 4; // 223552

__device__ __forceinline__ unsigned smem_u32(const void* p) {
    return (unsigned)__cvta_generic_to_shared(p);
}
__device__ __forceinline__ float sigmoidf_(float x) {
    return 1.0f / (1.0f + __expf(-x));
}
__device__ __forceinline__ void mbar_wait(unsigned addr, int phase) {
    asm volatile(
        "{\n\t.reg .pred P;\n\t"
        "W_%=:\n\t"
        "mbarrier.try_wait.parity.acquire.cta.shared::cta.b64 P, [%0], %1, 0x989680;\n\t"
        "@P bra.uni D_%=;\n\t"
        "bra.uni W_%=;\n\t"
        "D_%=:\n\t}"
        :: "r"(addr), "r"((unsigned)phase) : "memory");
}

// Issue the 3 bulk-copy chunks for tile g into buffer p (tid 0 only).
__device__ __forceinline__ void issue_tile(const float* __restrict__ s_pair,
                                           int g, float* buf, unsigned mbar0)
{
    asm volatile("fence.proxy.async.shared::cta;" ::: "memory");
    const bool valid = (g < NTILES);
    const int  i = valid ? (g % NDIM) : 0;
    const int  rowStart = i + 1;
    const int  nRows = NDIM - rowStart;
    const float* src0 = s_pair + (size_t)g * (NDIM * NDIM)
                      + (size_t)rowStart * NDIM;
    #pragma unroll
    for (int c = 0; c < 3; ++c) {
        int nr = nRows - c * CHROWS;
        if (nr > CHROWS) nr = CHROWS;
        unsigned bytes = (valid && nr > 0) ? (unsigned)(nr * NDIM * 4) : 0u;
        unsigned mb = mbar0 + 8 * c;
        asm volatile("mbarrier.arrive.expect_tx.shared.b64 _, [%0], %1;"
                     :: "r"(mb), "r"(bytes) : "memory");
        if (bytes) {
            unsigned dst = smem_u32(buf + c * (CHROWS * NDIM));
            asm volatile(
                "cp.async.bulk.shared::cta.global.mbarrier::complete_tx::bytes "
                "[%0], [%1], %2, [%3];"
                :: "r"(dst), "l"(src0 + c * (CHROWS * NDIM)), "r"(bytes), "r"(mb)
                : "memory");
        }
    }
}

__global__ void __launch_bounds__(THREADS, 1)
mfvi_kernel(const float* __restrict__ s_span,
            const float* __restrict__ s_pair,
            float* __restrict__ out)
{
    extern __shared__ float smem[];
    uint64_t* mbar = reinterpret_cast<uint64_t*>(smem);   // [2][3]
    float* bufs    = smem + MBARF;                        // [2][BUF_FLOATS]
    float* sigA    = bufs + 2 * BUF_FLOATS;               // [192]
    float* sigB    = sigA + NDIM;                         // [192]
    float* partial = sigB + NDIM;                         // [192]

    const int tid = threadIdx.x;
    const int hw  = tid >> 4;        // half-warp 0..47: rows hw + 48t
    const int ll  = tid & 15;

    if (tid == 0) {
        #pragma unroll
        for (int s = 0; s < 6; ++s)
            asm volatile("mbarrier.init.shared.b64 [%0], 1;"
                         :: "r"(smem_u32(&mbar[s])) : "memory");
        asm volatile("fence.proxy.async.shared::cta;" ::: "memory");
    }
    __syncthreads();

    // Prologue: tile 0 into buffer 0.
    if (tid == 0)
        issue_tile(s_pair, blockIdx.x, bufs, smem_u32(&mbar[0]));

    int n = 0;
    for (int g = blockIdx.x; g < NTILES; g += gridDim.x, ++n) {
        const int p  = n & 1;
        const int ph = (n >> 1) & 1;
        float* buf = bufs + p * BUF_FLOATS;
        const unsigned mb0 = smem_u32(&mbar[3 * p]);

        // Start next tile's load into the other (already-consumed) buffer.
        if (tid == 0)
            issue_tile(s_pair, g + gridDim.x, bufs + (p ^ 1) * BUF_FLOATS,
                       smem_u32(&mbar[3 * (p ^ 1)]));

        const int i        = g % NDIM;
        const int rowStart = i + 1;
        const int nRows    = NDIM - rowStart;
        const float* gbase = s_pair + (size_t)g * (NDIM * NDIM);

        // span / sig0 / mask-correction scalars
        float span_j = 0.0f, s_prev = 0.5f, vi = 0.0f, vjj = 0.0f;
        if (tid < NDIM) {
            span_j = s_span[(size_t)g * NDIM + tid];
            s_prev = sigmoidf_(span_j);
            sigA[tid] = s_prev;
            sigB[tid] = s_prev;       // k<=i entries stay s0 in both buffers
            if (tid > i) {
                vi  = __ldg(gbase + (size_t)tid * NDIM + i);
                vjj = __ldg(gbase + (size_t)tid * NDIM + tid);
            }
        }
        __syncthreads();
        const float s0i = sigA[i];    // sig[i] constant across iterations

        #pragma unroll
        for (int it = 0; it < 3; ++it) {
            const float* sg = (it == 1) ? sigB : sigA;
            const float4* sg4 = reinterpret_cast<const float4*>(sg);
            const float4 s0 = sg4[ll], s1 = sg4[ll + 16], s2 = sg4[ll + 32];

            float d[4] = {0.f, 0.f, 0.f, 0.f};

            // t = 3: overflow rows straight from gmem/L2 (overlaps TMA in it 0)
            {
                const int r = hw + 3 * CHROWS;
                if (r < nRows) {
                    const float4* rp = reinterpret_cast<const float4*>(
                        gbase + (size_t)(rowStart + r) * NDIM);
                    float4 a = __ldg(rp + ll), b = __ldg(rp + ll + 16),
                           e = __ldg(rp + ll + 32);
                    d[3] = a.x * s0.x + a.y * s0.y + a.z * s0.z + a.w * s0.w
                         + b.x * s1.x + b.y * s1.y + b.z * s1.z + b.w * s1.w
                         + e.x * s2.x + e.y * s2.y + e.z * s2.z + e.w * s2.w;
                }
            }
            // t = 0..2: SMEM chunks (wait bulk-copy arrival only in it 0)
            #pragma unroll
            for (int c = 0; c < 3; ++c) {
                if (it == 0) mbar_wait(mb0 + 8 * c, ph);
                const int r = hw + c * CHROWS;
                if (r < nRows) {
                    const float4* rp = reinterpret_cast<const float4*>(
                        buf + (size_t)r * NDIM);
                    float4 a = rp[ll], b = rp[ll + 16], e = rp[ll + 32];
                    d[c] = a.x * s0.x + a.y * s0.y + a.z * s0.z + a.w * s0.w
                         + b.x * s1.x + b.y * s1.y + b.z * s1.z + b.w * s1.w
                         + e.x * s2.x + e.y * s2.y + e.z * s2.z + e.w * s2.w;
                }
            }
            // 16-lane row reductions (both half-warps concurrently)
            #pragma unroll
            for (int off = 8; off >= 1; off >>= 1)
                #pragma unroll
                for (int t = 0; t < 4; ++t)
                    d[t] += __shfl_xor_sync(0xffffffffu, d[t], off);
            #pragma unroll
            for (int t = 0; t < 4; ++t) {
                const int r = hw + t * CHROWS;
                if (ll == t && r < nRows) partial[r] = d[t];
            }
            __syncthreads();

            if (tid < NDIM) {
                if (tid > i) {
                    float q = span_j + partial[tid - rowStart]
                            - s0i * vi - s_prev * vjj;
                    s_prev = sigmoidf_(q);
                    if (it == 0) sigB[tid] = s_prev;
                    else if (it == 1) sigA[tid] = s_prev;
                }
                if (it == 2) out[(size_t)g * NDIM + tid] = s_prev;
            }
            __syncthreads();
        }
    }
}

extern "C" void kernel_launch(void* const* d_in, const int* in_sizes, int n_in,
                              void* d_out, int out_size)
{
    (void)in_sizes; (void)n_in; (void)out_size;
    const float* s_span = (const float*)d_in[0];
    const float* s_pair = (const float*)d_in[1];
    // d_in[2] = mask: analytic (strict upper triangle), not needed.
    float* out = (float*)d_out;

    int nsm = 148;
    cudaDeviceGetAttribute(&nsm, cudaDevAttrMultiProcessorCount, 0);
    if (nsm <= 0 || nsm > NTILES) nsm = 148;

    cudaFuncSetAttribute(mfvi_kernel,
                         cudaFuncAttributeMaxDynamicSharedMemorySize, SMEM_BYTES);

    mfvi_kernel<<<nsm, THREADS, SMEM_BYTES>>>(s_span, s_pair, out);
}

// round 11
// speedup vs baseline: 2.1429x; 1.2951x over previous
#include <cuda_runtime.h>
#include <cstdint>

// ConstituencyMFVI: B=8, N=192, 3 iterations.
// R11: TWO independent CTAs per SM (512 thr, 100.6KB smem each) so one CTA's
// phase-locked serial latency (barriers, mbar waits, shfl chains, combiner)
// is hidden by the other's throughput work -- the ~9K cyc/tile plateau of
// all 1-CTA/SM designs was latency serialization, not pipe limits.
// Tile load via cp.async.bulk (4 chunks x 32 rows) into a SINGLE buffer;
// cross-tile overlap comes from the sibling CTA. Rows >=128 (only i<63)
// dotted from gmem/L2. Half-warp-per-row consume (lane ll reads f4 cols
// {ll,ll+16,ll+32}, conflict-free, unpadded) + 4-step shfl_xor reduce.

#define NDIM    192
#define CROWS   128
#define THREADS 512
#define NTILES  (8 * NDIM)          // 1536
#define BUF_FLOATS (CROWS * NDIM)   // 24576

static const int SMEM_BYTES = (8 + BUF_FLOATS + 3 * NDIM) * 4;   // 100640

__device__ __forceinline__ unsigned smem_u32(const void* p) {
    return (unsigned)__cvta_generic_to_shared(p);
}
__device__ __forceinline__ float sigmoidf_(float x) {
    return 1.0f / (1.0f + __expf(-x));
}
__device__ __forceinline__ void mbar_wait(unsigned addr, int phase) {
    asm volatile(
        "{\n\t.reg .pred P;\n\t"
        "W_%=:\n\t"
        "mbarrier.try_wait.parity.acquire.cta.shared::cta.b64 P, [%0], %1, 0x989680;\n\t"
        "@P bra.uni D_%=;\n\t"
        "bra.uni W_%=;\n\t"
        "D_%=:\n\t}"
        :: "r"(addr), "r"((unsigned)phase) : "memory");
}

// Issue 4 bulk-copy chunks (32 rows each) for tile g (tid 0 only).
__device__ __forceinline__ void issue_tile(const float* __restrict__ s_pair,
                                           int g, float* buf, unsigned mbar0)
{
    asm volatile("fence.proxy.async.shared::cta;" ::: "memory");
    const bool valid = (g < NTILES);
    const int  i = valid ? (g % NDIM) : 0;
    const int  nRows = NDIM - 1 - i;
    const float* src0 = s_pair + (size_t)g * (NDIM * NDIM)
                      + (size_t)(i + 1) * NDIM;
    #pragma unroll
    for (int c = 0; c < 4; ++c) {
        int nr = nRows - c * 32;
        if (nr > 32) nr = 32;
        unsigned bytes = (valid && nr > 0) ? (unsigned)(nr * NDIM * 4) : 0u;
        unsigned mb = mbar0 + 8 * c;
        asm volatile("mbarrier.arrive.expect_tx.shared.b64 _, [%0], %1;"
                     :: "r"(mb), "r"(bytes) : "memory");
        if (bytes) {
            unsigned dst = smem_u32(buf + c * (32 * NDIM));
            asm volatile(
                "cp.async.bulk.shared::cta.global.mbarrier::complete_tx::bytes "
                "[%0], [%1], %2, [%3];"
                :: "r"(dst), "l"(src0 + c * (32 * NDIM)), "r"(bytes), "r"(mb)
                : "memory");
        }
    }
}

__global__ void __launch_bounds__(THREADS, 2)
mfvi_kernel(const float* __restrict__ s_span,
            const float* __restrict__ s_pair,
            float* __restrict__ out)
{
    extern __shared__ float smem[];
    uint64_t* mbar = reinterpret_cast<uint64_t*>(smem);   // [4]
    float* buf     = smem + 8;                            // [128][192]
    float* sigA    = buf + BUF_FLOATS;                    // [192]
    float* sigB    = sigA + NDIM;                         // [192]
    float* partial = sigB + NDIM;                         // [192]

    const int tid = threadIdx.x;
    const int hw  = tid >> 4;        // half-warp 0..31
    const int ll  = tid & 15;
    const unsigned mb0 = smem_u32(&mbar[0]);

    if (tid == 0) {
        #pragma unroll
        for (int s = 0; s < 4; ++s)
            asm volatile("mbarrier.init.shared.b64 [%0], 1;"
                         :: "r"(smem_u32(&mbar[s])) : "memory");
        asm volatile("fence.proxy.async.shared::cta;" ::: "memory");
    }
    __syncthreads();

    if (tid == 0)
        issue_tile(s_pair, blockIdx.x, buf, mb0);

    int n = 0;
    for (int g = blockIdx.x; g < NTILES; g += gridDim.x, ++n) {
        const int ph = n & 1;
        const int i        = g % NDIM;
        const int rowStart = i + 1;
        const int nRows    = NDIM - rowStart;
        const float* gbase = s_pair + (size_t)g * (NDIM * NDIM);

        float span_j = 0.0f, s_prev = 0.5f, vi = 0.0f, vjj = 0.0f;
        if (tid < NDIM) {
            span_j = s_span[(size_t)g * NDIM + tid];
            s_prev = sigmoidf_(span_j);
            sigA[tid] = s_prev;
            sigB[tid] = s_prev;      // k<=i entries stay sig0 in both buffers
        }
        __syncthreads();
        const float s0i = sigA[i];   // sig[i] constant across iterations

        #pragma unroll
        for (int it = 0; it < 3; ++it) {
            const float* sg = (it == 1) ? sigB : sigA;
            const float4* sg4 = reinterpret_cast<const float4*>(sg);
            const float4 s0 = sg4[ll], s1 = sg4[ll + 16], s2 = sg4[ll + 32];

            float d[6] = {0.f, 0.f, 0.f, 0.f, 0.f, 0.f};

            // Overflow rows (r = 128+hw, 160+hw) from gmem/L2 first:
            // their latency overlaps the chunk mbar waits in it==0.
            #pragma unroll
            for (int ov = 0; ov < 2; ++ov) {
                const int r = CROWS + 32 * ov + hw;
                if (r < nRows) {
                    const float4* rp = reinterpret_cast<const float4*>(
                        gbase + (size_t)(rowStart + r) * NDIM);
                    float4 a = __ldg(rp + ll), b = __ldg(rp + ll + 16),
                           e = __ldg(rp + ll + 32);
                    d[4 + ov] =
                          a.x * s0.x + a.y * s0.y + a.z * s0.z + a.w * s0.w
                        + b.x * s1.x + b.y * s1.y + b.z * s1.z + b.w * s1.w
                        + e.x * s2.x + e.y * s2.y + e.z * s2.z + e.w * s2.w;
                }
            }
            // SMEM chunks: chunk c holds exactly rows 32c..32c+31 (t == c).
            #pragma unroll
            for (int c = 0; c < 4; ++c) {
                if (it == 0) mbar_wait(mb0 + 8 * c, ph);
                const int r = hw + 32 * c;
                if (r < nRows) {
                    const float4* rp = reinterpret_cast<const float4*>(
                        buf + (size_t)r * NDIM);
                    float4 a = rp[ll], b = rp[ll + 16], e = rp[ll + 32];
                    d[c] = a.x * s0.x + a.y * s0.y + a.z * s0.z + a.w * s0.w
                         + b.x * s1.x + b.y * s1.y + b.z * s1.z + b.w * s1.w
                         + e.x * s2.x + e.y * s2.y + e.z * s2.z + e.w * s2.w;
                }
            }
            #pragma unroll
            for (int off = 8; off >= 1; off >>= 1)
                #pragma unroll
                for (int t = 0; t < 6; ++t)
                    d[t] += __shfl_xor_sync(0xffffffffu, d[t], off);
            #pragma unroll
            for (int t = 0; t < 6; ++t) {
                const int r = (t < 4) ? (hw + 32 * t) : (CROWS + 32 * (t - 4) + hw);
                if (ll == t && r < nRows) partial[r] = d[t];
            }
            __syncthreads();

            // All iter-3 buffer reads done -> start next tile's TMA now.
            if (it == 2 && tid == 0)
                issue_tile(s_pair, g + gridDim.x, buf, mb0);

            if (it == 0 && tid < NDIM && tid > i) {
                // mask-correction scalars, read once (data now resident)
                const int r = tid - rowStart;
                if (r < CROWS) {
                    vi  = buf[(size_t)r * NDIM + i];
                    vjj = buf[(size_t)r * NDIM + tid];
                } else {
                    vi  = __ldg(gbase + (size_t)tid * NDIM + i);
                    vjj = __ldg(gbase + (size_t)tid * NDIM + tid);
                }
            }
            if (tid < NDIM) {
                if (tid > i) {
                    float q = span_j + partial[tid - rowStart]
                            - s0i * vi - s_prev * vjj;
                    s_prev = sigmoidf_(q);
                    if (it == 0) sigB[tid] = s_prev;
                    else if (it == 1) sigA[tid] = s_prev;
                }
                if (it == 2) out[(size_t)g * NDIM + tid] = s_prev;
            }
            __syncthreads();
        }
    }
}

extern "C" void kernel_launch(void* const* d_in, const int* in_sizes, int n_in,
                              void* d_out, int out_size)
{
    (void)in_sizes; (void)n_in; (void)out_size;
    const float* s_span = (const float*)d_in[0];
    const float* s_pair = (const float*)d_in[1];
    // d_in[2] = mask: analytic (strict upper triangle), not needed.
    float* out = (float*)d_out;

    int nsm = 148;
    cudaDeviceGetAttribute(&nsm, cudaDevAttrMultiProcessorCount, 0);
    if (nsm <= 0) nsm = 148;
    int grid = 2 * nsm;                 // 2 persistent CTAs per SM
    if (grid > NTILES) grid = NTILES;

    cudaFuncSetAttribute(mfvi_kernel,
                         cudaFuncAttributeMaxDynamicSharedMemorySize, SMEM_BYTES);

    mfvi_kernel<<<grid, THREADS, SMEM_BYTES>>>(s_span, s_pair, out);
}